// round 11
// baseline (speedup 1.0000x reference)
#include <cuda_runtime.h>
#include <cstdint>

#define T_STEPS 2000
#define BATCH   256
#define SEQ     10000
#define KW      5

typedef unsigned long long ull;

// Gate pre-activations a_x[t][b][j], stored so float2 at (t*256+b)*32 + l =
// { a[j=l], a[j=l+32] }. Padded by 2 timesteps for branchless prefetch.
__device__ float g_ax[(size_t)(T_STEPS + 2) * BATCH * 64];

__device__ __forceinline__ float tanhap(float x) {
    float r; asm("tanh.approx.f32 %0, %1;" : "=f"(r) : "f"(x)); return r;
}

// ---- f32x2 packed helpers (sm_103a) --------------------------------------
__device__ __forceinline__ ull pk2(float lo, float hi) {
    ull r; asm("mov.b64 %0, {%1, %2};" : "=l"(r) : "f"(lo), "f"(hi)); return r;
}
__device__ __forceinline__ void upk2(float& lo, float& hi, ull v) {
    asm("mov.b64 {%0, %1}, %2;" : "=f"(lo), "=f"(hi) : "l"(v));
}
__device__ __forceinline__ ull ffma2(ull a, ull b, ull c) {
    ull r; asm("fma.rn.f32x2 %0, %1, %2, %3;" : "=l"(r) : "l"(a), "l"(b), "l"(c)); return r;
}
__device__ __forceinline__ ull fadd2(ull a, ull b) {
    ull r; asm("add.rn.f32x2 %0, %1, %2;" : "=l"(r) : "l"(a), "l"(b)); return r;
}
__device__ __forceinline__ ull fmul2(ull a, ull b) {
    ull r; asm("mul.rn.f32x2 %0, %1, %2;" : "=l"(r) : "l"(a), "l"(b)); return r;
}

__device__ __forceinline__ float sigf_exact(float x) {
    return __fdividef(1.0f, 1.0f + __expf(-x));
}

// ---- ordered smem access ----
__device__ __forceinline__ uint32_t smem_u32(const void* p) {
    uint32_t a;
    asm("{ .reg .u64 t; cvta.to.shared.u64 t, %1; cvt.u32.u64 %0, t; }"
        : "=r"(a) : "l"(p));
    return a;
}
__device__ __forceinline__ void sts_f32(uint32_t a, float v) {
    asm volatile("st.shared.f32 [%0], %1;" :: "r"(a), "f"(v) : "memory");
}
__device__ __forceinline__ void sts_v2(uint32_t a, float x, float y) {
    asm volatile("st.shared.v2.f32 [%0], {%1, %2};" :: "r"(a), "f"(x), "f"(y) : "memory");
}
// vector 128-bit load: two ulls in one LDS.128, no repacking movs
__device__ __forceinline__ void lds_v2u64(uint32_t a, ull& x, ull& y) {
    asm("ld.shared.v2.u64 {%0, %1}, [%2];" : "=l"(x), "=l"(y) : "r"(a) : "memory");
}
__device__ __forceinline__ float4 lds_v4(uint32_t a) {
    float4 v;
    asm("ld.shared.v4.f32 {%0, %1, %2, %3}, [%4];"
        : "=f"(v.x), "=f"(v.y), "=f"(v.z), "=f"(v.w) : "r"(a) : "memory");
    return v;
}

// ---------------------------------------------------------------------------
// Pre-pass (unchanged from R10 measured-best): one THREAD per (t, b).
// ---------------------------------------------------------------------------
__global__ void __launch_bounds__(128) prepass_kernel(
    const float* __restrict__ x,  const float* __restrict__ Wm,
    const float* __restrict__ bm, const float* __restrict__ Wc,
    const float* __restrict__ bconv, const float* __restrict__ Wx,
    const float* __restrict__ gx, const float* __restrict__ bx,
    const float* __restrict__ bg)
{
    __shared__ float sP[80], sN[80], sbc[16];
    __shared__ float sWm[16], sbm[16], scmx[16];
    __shared__ int   sbmnz;
    __shared__ float sWcT[80 * 16];
    __shared__ ull sWxT2[16][32];
    __shared__ ull sgx2[32], sbxg2[32];
    __shared__ float2 stage[4][32][33];

    if (threadIdx.x == 0) {
        int nz = 0;
        for (int i = 0; i < 16; i++) if (bm[i] != 0.0f) nz = 1;
        sbmnz = nz;
    }
    if (threadIdx.x < 80) {
        int o = threadIdx.x / 5, k = threadIdx.x % 5;
        float p = 0.0f, n = 0.0f;
        for (int i = 0; i < 16; i++) {
            float w = __ldg(&Wm[i]);
            float c = __ldg(&Wc[o * 80 + i * 5 + k]);
            if (w > 0.0f) p = fmaf(c, w, p);
            else if (w < 0.0f) n = fmaf(c, w, n);
        }
        sP[threadIdx.x] = p;
        sN[threadIdx.x] = n;
    }
    if (threadIdx.x >= 96 && threadIdx.x < 112) {
        int col = threadIdx.x - 96;
        float s = 0.0f;
        for (int j = 0; j < 64; j++) s += __ldg(&Wx[j * 16 + col]);
        scmx[col] = s * (1.0f / 64.0f);
    }
    for (int i = threadIdx.x; i < 16; i += blockDim.x) {
        sbc[i] = bconv[i]; sWm[i] = Wm[i]; sbm[i] = bm[i];
    }
    for (int i = threadIdx.x; i < 80 * 16; i += blockDim.x) {
        int ik = i >> 4, o = i & 15;
        sWcT[i] = Wc[o * 80 + ik];
    }
    for (int i = threadIdx.x; i < 32; i += blockDim.x) {
        sgx2[i]  = pk2(gx[i], gx[i + 32]);
        sbxg2[i] = pk2(bx[i] + bg[i], bx[i + 32] + bg[i + 32]);
    }
    __syncthreads();

    for (int i = threadIdx.x; i < 16 * 32; i += blockDim.x) {
        int o = i >> 5, l = i & 31;
        sWxT2[o][l] = pk2(Wx[l * 16 + o] - scmx[o],
                          Wx[(l + 32) * 16 + o] - scmx[o]);
    }
    __syncthreads();

    const int bmnz = sbmnz;
    int lane = threadIdx.x & 31;
    int wrp  = threadIdx.x >> 5;
    int b    = blockIdx.y;
    int tbase = blockIdx.x * 128 + wrp * 32;
    int t     = tbase + lane;
    int tt = (t < T_STEPS) ? t : 0;

    float xt[16];
    #pragma unroll
    for (int o = 0; o < 16; o++) xt[o] = sbc[o];

    if (!bmnz) {
        #pragma unroll
        for (int k = 0; k < KW; k++) {
            float xk = __ldg(&x[b * SEQ + tt * KW + k]);
            const float* PN = (xk > 0.0f) ? sP : sN;
            #pragma unroll
            for (int o = 0; o < 16; o++)
                xt[o] = fmaf(xk, PN[o * 5 + k], xt[o]);
        }
    } else {
        #pragma unroll
        for (int k = 0; k < KW; k++) {
            float xk = __ldg(&x[b * SEQ + tt * KW + k]);
            #pragma unroll
            for (int i = 0; i < 16; i++) {
                float f = fmaxf(fmaf(xk, sWm[i], sbm[i]), 0.0f);
                const float4* wr = (const float4*)&sWcT[(i * KW + k) * 16];
                #pragma unroll
                for (int o4 = 0; o4 < 4; o4++) {
                    float4 w = wr[o4];
                    xt[o4 * 4 + 0] = fmaf(w.x, f, xt[o4 * 4 + 0]);
                    xt[o4 * 4 + 1] = fmaf(w.y, f, xt[o4 * 4 + 1]);
                    xt[o4 * 4 + 2] = fmaf(w.z, f, xt[o4 * 4 + 2]);
                    xt[o4 * 4 + 3] = fmaf(w.w, f, xt[o4 * 4 + 3]);
                }
            }
        }
    }
    #pragma unroll
    for (int o = 0; o < 16; o++) xt[o] = sigf_exact(xt[o]);

    ull y2[32];
    #pragma unroll
    for (int l = 0; l < 32; l++) y2[l] = 0ull;
    #pragma unroll
    for (int o = 0; o < 16; o++) {
        ull x2 = pk2(xt[o], xt[o]);
        #pragma unroll
        for (int l = 0; l < 32; l++)
            y2[l] = ffma2(sWxT2[o][l], x2, y2[l]);
    }

    ull q2a = 0ull, q2b = 0ull;
    #pragma unroll
    for (int l = 0; l < 32; l += 2) {
        q2a = ffma2(y2[l],     y2[l],     q2a);
        q2b = ffma2(y2[l + 1], y2[l + 1], q2b);
    }
    float qa, qb, qc, qd;
    upk2(qa, qb, q2a); upk2(qc, qd, q2b);
    float q = (qa + qb) + (qc + qd);
    float r = rsqrtf(q * (1.0f / 64.0f) + 1e-5f);

    ull r2 = pk2(r, r);
    #pragma unroll
    for (int l = 0; l < 32; l++) {
        ull tnorm = fmul2(y2[l], r2);
        ull a2    = ffma2(tnorm, sgx2[l], sbxg2[l]);
        float a0, a1; upk2(a0, a1, a2);
        stage[wrp][lane][l] = make_float2(a0, a1);
    }
    __syncwarp();

    float2* gax2 = (float2*)g_ax;
    #pragma unroll 4
    for (int k = 0; k < 32; k++) {
        int tk = tbase + k;
        if (tk < T_STEPS)
            gax2[((size_t)tk * 256 + b) * 32 + lane] = stage[wrp][k][lane];
    }
}

// ---------------------------------------------------------------------------
// Sequential LSTM scan. ONE warp = ONE row; branch-free, sync-free body
// (R10 structure). New in R11:
//   - gather trees load 2 ulls per LDS.128 (8 loads/tree, was 16)
//   - all "upper ?" sigmoid/tanh scalings folded into per-lane constants
//     outside the loop; gate constants pre-scaled so the post-r chain is
//     one FMA -> MUFU -> FMA; off-chain products computed during gathers.
// ---------------------------------------------------------------------------
__global__ void __launch_bounds__(32) lstm_seq_kernel(
    const float* __restrict__ Wh,   const float* __restrict__ gh,
    const float* __restrict__ bh,   const float* __restrict__ gc,
    const float* __restrict__ bc,   const float* __restrict__ Wcls,
    const float* __restrict__ bcls, const float* __restrict__ h0,
    const float* __restrict__ c0,   float* __restrict__ out)
{
    const unsigned ALL = 0xffffffffu;
    int lane  = threadIdx.x;
    int m     = lane & 15;
    bool upper = lane >= 16;
    int row   = blockIdx.x;

    __shared__ __align__(16) float  smean[16];
    __shared__ __align__(16) float  shv32[32];   // h: all lanes store, read 16..31
    __shared__ __align__(16) float  sqp[32];     // q partials
    __shared__ __align__(16) float2 scq32[32];   // (c, c^2): read 16..31

    // prologue: Wh column means
    {
        float s = 0.0f;
        #pragma unroll 8
        for (int j = 0; j < 64; j++) s += __ldg(&Wh[j * 16 + m]);
        if (!upper) smean[m] = s * (1.0f / 64.0f);
    }
    __syncwarp();

    float wa[16], wb[16];
    #pragma unroll
    for (int i = 0; i < 16; i++) {
        float cm = smean[i];
        wa[i] = __ldg(&Wh[lane * 16 + i]) - cm;
        wb[i] = __ldg(&Wh[(lane + 32) * 16 + i]) - cm;
    }
    // gate constants, pre-scaled for single-MUFU nonlinearities:
    //   u1 = sig(ga): arg = 0.5*ga  -> fold 0.5 into gha/bha/cur.x
    //   u2 = upper ? sig(gb) : tanh(gb): arg = sgb*gb, out = fmaf(oa, t, ob)
    float sgb = upper ? 0.5f : 1.0f;
    float oa  = upper ? 0.5f : 1.0f;
    float ob  = upper ? 0.5f : 0.0f;
    float ghah = gh[lane] * 0.5f,        bhah = bh[lane] * 0.5f;
    float ghbs = gh[lane + 32] * sgb,    bhbs = bh[lane + 32] * sgb;
    float gcm = gc[m], bcm = bc[m];

    float h = h0[row * 16 + m];
    float c = c0[row * 16 + m];

    uint32_t shv_w = smem_u32(shv32) + lane * 4;
    uint32_t shv_r = smem_u32(shv32) + 64;        // &shv32[16]
    uint32_t sqp_w = smem_u32(sqp) + lane * 4;
    uint32_t sqp_r = smem_u32(sqp);
    uint32_t scq_w = smem_u32(scq32) + lane * 8;
    uint32_t scq_r = smem_u32(scq32) + 128;       // &scq32[16]

    sts_f32(shv_w, h);

    const float2* ax = (const float2*)g_ax;
    const int stride = BATCH * 32;
    const float2* pf = ax + row * 32 + lane;
    float2 p0 = pf[0];
    float2 p1 = pf[stride];
    pf += 2 * stride;

    #pragma unroll 2
    for (int t = 0; t < T_STEPS; t++) {
        // --- h broadcast ---
        float4 hv0 = lds_v4(shv_r);
        float4 hv1 = lds_v4(shv_r + 16);
        float4 hv2 = lds_v4(shv_r + 32);
        float4 hv3 = lds_v4(shv_r + 48);

        float2 cur = p0;
        p0 = p1;
        p1 = *pf;
        pf += stride;

        // --- centered matvec (4 independent FMA chains) ---
        float ya0, ya1, yb0, yb1;
        ya0 = wa[0] * hv0.x; ya1 = wa[1] * hv0.y;
        yb0 = wb[0] * hv0.x; yb1 = wb[1] * hv0.y;
        ya0 = fmaf(wa[2],  hv0.z, ya0); ya1 = fmaf(wa[3],  hv0.w, ya1);
        yb0 = fmaf(wb[2],  hv0.z, yb0); yb1 = fmaf(wb[3],  hv0.w, yb1);
        ya0 = fmaf(wa[4],  hv1.x, ya0); ya1 = fmaf(wa[5],  hv1.y, ya1);
        yb0 = fmaf(wb[4],  hv1.x, yb0); yb1 = fmaf(wb[5],  hv1.y, yb1);
        ya0 = fmaf(wa[6],  hv1.z, ya0); ya1 = fmaf(wa[7],  hv1.w, ya1);
        yb0 = fmaf(wb[6],  hv1.z, yb0); yb1 = fmaf(wb[7],  hv1.w, yb1);
        ya0 = fmaf(wa[8],  hv2.x, ya0); ya1 = fmaf(wa[9],  hv2.y, ya1);
        yb0 = fmaf(wb[8],  hv2.x, yb0); yb1 = fmaf(wb[9],  hv2.y, yb1);
        ya0 = fmaf(wa[10], hv2.z, ya0); ya1 = fmaf(wa[11], hv2.w, ya1);
        yb0 = fmaf(wb[10], hv2.z, yb0); yb1 = fmaf(wb[11], hv2.w, yb1);
        ya0 = fmaf(wa[12], hv3.x, ya0); ya1 = fmaf(wa[13], hv3.y, ya1);
        yb0 = fmaf(wb[12], hv3.x, yb0); yb1 = fmaf(wb[13], hv3.y, yb1);
        ya0 = fmaf(wa[14], hv3.z, ya0); ya1 = fmaf(wa[15], hv3.w, ya1);
        yb0 = fmaf(wb[14], hv3.z, yb0); yb1 = fmaf(wb[15], hv3.w, yb1);
        float ya = ya0 + ya1;
        float yb = yb0 + yb1;

        // --- var reduction (gather1): STS then 8x LDS.128 tree ---
        sts_f32(sqp_w, fmaf(ya, ya, yb * yb));
        ull a0, a1, b0, b1, c0_, c1, d0, d1, e0, e1, f0, f1, g0, g1, h0_, h1;
        lds_v2u64(sqp_r,       a0, a1);
        lds_v2u64(sqp_r + 16,  b0, b1);
        lds_v2u64(sqp_r + 32,  c0_, c1);
        lds_v2u64(sqp_r + 48,  d0, d1);
        lds_v2u64(sqp_r + 64,  e0, e1);
        lds_v2u64(sqp_r + 80,  f0, f1);
        lds_v2u64(sqp_r + 96,  g0, g1);
        lds_v2u64(sqp_r + 112, h0_, h1);

        // off-chain gate prep (overlaps the gather loads)
        float pya = ya * ghah;                 // ya * gh/2
        float pyb = yb * ghbs;                 // yb * gh*sgb
        float k1  = fmaf(cur.x, 0.5f, bhah);   // (bh + a_x)/2
        float k2  = fmaf(cur.y, sgb,  bhbs);   // (bh + a_x)*sgb

        ull t0 = fadd2(a0, a1);
        ull t1 = fadd2(b0, b1);
        ull t2 = fadd2(c0_, c1);
        ull t3 = fadd2(d0, d1);
        ull t4 = fadd2(e0, e1);
        ull t5 = fadd2(f0, f1);
        ull t6 = fadd2(g0, g1);
        ull t7 = fadd2(h0_, h1);
        t0 = fadd2(t0, t1); t2 = fadd2(t2, t3);
        t4 = fadd2(t4, t5); t6 = fadd2(t6, t7);
        t0 = fadd2(fadd2(t0, t2), fadd2(t4, t6));
        float qlo, qhi; upk2(qlo, qhi, t0);
        float r = rsqrtf((qlo + qhi) * (1.0f / 64.0f) + 1e-5f);

        // post-r chain: one FMA each -> MUFU -> one FMA
        float u1 = fmaf(0.5f, tanhap(fmaf(pya, r, k1)), 0.5f);  // sig(i)|sig(f)
        float u2 = fmaf(oa,   tanhap(fmaf(pyb, r, k2)), ob);    // tanh(g)|sig(o)
        float Aval = u1 * u2;                                   // lower: sig(i)tanh(g)
        float A = __shfl_xor_sync(ALL, Aval, 16);

        c = fmaf(u1, c, A);                                     // valid on upper
        sts_v2(scq_w, c, c * c);

        // --- LN16 stats (gather2): 8x LDS.128 tree ---
        ull s0a, s0b, s1a, s1b, s2a, s2b, s3a, s3b;
        ull s4a, s4b, s5a, s5b, s6a, s6b, s7a, s7b;
        lds_v2u64(scq_r,       s0a, s0b);
        lds_v2u64(scq_r + 16,  s1a, s1b);
        lds_v2u64(scq_r + 32,  s2a, s2b);
        lds_v2u64(scq_r + 48,  s3a, s3b);
        lds_v2u64(scq_r + 64,  s4a, s4b);
        lds_v2u64(scq_r + 80,  s5a, s5b);
        lds_v2u64(scq_r + 96,  s6a, s6b);
        lds_v2u64(scq_r + 112, s7a, s7b);
        ull s0 = fadd2(s0a, s0b);
        ull s1 = fadd2(s1a, s1b);
        ull s2 = fadd2(s2a, s2b);
        ull s3 = fadd2(s3a, s3b);
        ull s4 = fadd2(s4a, s4b);
        ull s5 = fadd2(s5a, s5b);
        ull s6 = fadd2(s6a, s6b);
        ull s7 = fadd2(s7a, s7b);
        s0 = fadd2(s0, s1); s2 = fadd2(s2, s3);
        s4 = fadd2(s4, s5); s6 = fadd2(s6, s7);
        s0 = fadd2(fadd2(s0, s2), fadd2(s4, s6));
        float sc, qc; upk2(sc, qc, s0);

        float mc = sc * (1.0f / 16.0f);
        float vc = fmaf(-mc, mc, qc * (1.0f / 16.0f));
        float rc = rsqrtf(vc + 1e-5f);
        float dcg = (c - mc) * gcm;            // overlaps the rsqrt
        float cn = fmaf(dcg, rc, bcm);
        h = u2 * tanhap(cn);                   // sig(o)*tanh(cn), upper valid
        sts_f32(shv_w, h);
    }

    // classifier
    float v = upper ? h * Wcls[m] : 0.0f;
    #pragma unroll
    for (int d = 16; d >= 1; d >>= 1)
        v += __shfl_xor_sync(ALL, v, d);
    if (lane == 0)
        out[row] = sigf_exact(v + bcls[0]);
}

// ---------------------------------------------------------------------------
extern "C" void kernel_launch(void* const* d_in, const int* in_sizes, int n_in,
                              void* d_out, int out_size)
{
    const float* x     = (const float*)d_in[0];
    const float* Wm    = (const float*)d_in[1];
    const float* bm    = (const float*)d_in[2];
    const float* Wc    = (const float*)d_in[3];
    const float* bconv = (const float*)d_in[4];
    const float* Wx    = (const float*)d_in[5];
    const float* Wh    = (const float*)d_in[6];
    const float* bg    = (const float*)d_in[7];
    const float* gx    = (const float*)d_in[8];
    const float* bx    = (const float*)d_in[9];
    const float* gh    = (const float*)d_in[10];
    const float* bh    = (const float*)d_in[11];
    const float* gc    = (const float*)d_in[12];
    const float* bc    = (const float*)d_in[13];
    const float* Wcls  = (const float*)d_in[14];
    const float* bcls  = (const float*)d_in[15];
    const float* h0    = (const float*)d_in[16];
    const float* c0    = (const float*)d_in[17];
    float* out = (float*)d_out;

    dim3 pgrid((T_STEPS + 127) / 128, BATCH);
    prepass_kernel<<<pgrid, 128>>>(x, Wm, bm, Wc, bconv, Wx, gx, bx, bg);
    lstm_seq_kernel<<<BATCH, 32>>>(Wh, gh, bh, gc, bc, Wcls, bcls, h0, c0, out);
}